// round 3
// baseline (speedup 1.0000x reference)
#include <cuda_runtime.h>
#include <math.h>

#define NSEQ 256
#define CDIM 128
#define NHEAD 4
#define DHEAD 32
#define NROWS (NSEQ * NSEQ)

// ---------------- scratch (device globals; no allocation allowed) ----------------
__device__ float g_qkv[(size_t)NROWS * 3 * CDIM];   // 96 MB; also reused as proj output
__device__ float g_attn[(size_t)NROWS * CDIM];      // 32 MB
__device__ float g_sums[NSEQ * CDIM];               // row/col prefix sums
__device__ float g_h1[NSEQ * 2 * CDIM];
__device__ float g_h2[NSEQ * CDIM];
__device__ unsigned char g_mask[NSEQ * NSEQ];

// ---------------- helpers ----------------
__device__ __forceinline__ float warp_sum(float v) {
#pragma unroll
    for (int o = 16; o; o >>= 1) v += __shfl_xor_sync(0xffffffffu, v, o);
    return v;
}
__device__ __forceinline__ float warp_max(float v) {
#pragma unroll
    for (int o = 16; o; o >>= 1) v = fmaxf(v, __shfl_xor_sync(0xffffffffu, v, o));
    return v;
}

// ---------------- mask normalization (bool-bytes vs int32 ambiguity) ----------------
// If mask was serialized as int32, all bytes at idx%4!=0 are 0 (values are 0/1).
// If serialized as 1-byte bool, ~half of those 49152 bytes are 1. Deterministic.
__global__ void mask_norm_kernel(const unsigned char* __restrict__ m) {
    __shared__ int flag;
    int tid = threadIdx.x;
    if (tid == 0) flag = 0;
    __syncthreads();
    int local = 0;
    for (int idx = tid; idx < NSEQ * NSEQ; idx += blockDim.x)
        if ((idx & 3) && m[idx]) local = 1;
    if (local) atomicOr(&flag, 1);
    __syncthreads();
    int isBytes = flag;
    for (int idx = tid; idx < NSEQ * NSEQ; idx += blockDim.x)
        g_mask[idx] = isBytes ? m[idx] : m[4 * (size_t)idx];
}

// ---------------- prefix sums ----------------
// s[i,c] = sum_{k<i} pair[i,k,c]
__global__ void rowsum_kernel(const float* __restrict__ pair) {
    int i = blockIdx.x, c = threadIdx.x;
    const float* p = pair + (size_t)i * NSEQ * CDIM + c;
    float s = 0.f;
#pragma unroll 4
    for (int k = 0; k < i; k++) s += __ldg(&p[(size_t)k * CDIM]);
    g_sums[i * CDIM + c] = s;
}

// s[j,c] = sum_{k<j} pr[k,j,c]
__global__ void colsum_kernel(const float* __restrict__ pr) {
    int j = blockIdx.x, c = threadIdx.x;
    const float* p = pr + (size_t)j * CDIM + c;
    float s = 0.f;
#pragma unroll 4
    for (int k = 0; k < j; k++) s += __ldg(&p[(size_t)k * NSEQ * CDIM]);
    g_sums[j * CDIM + c] = s;
}

// ---------------- fused tri-update + LayerNorm (warp per (i,j) row) ----------------
// mode 0 (out): x = src[i,j,:] + single[j,:] + sums[i,:]
// mode 1 (in):  x = src[i,j,:] + single[i,:] + sums[j,:]
__global__ __launch_bounds__(256)
void trimix_ln_kernel(float* __restrict__ out, const float* __restrict__ src,
                      const float* __restrict__ single,
                      const float* __restrict__ g, const float* __restrict__ b,
                      int mode) {
    int lane = threadIdx.x & 31, warp = threadIdx.x >> 5;
    int row = blockIdx.x * 8 + warp;          // row = i*256 + j
    int i = row >> 8, j = row & 255;
    const float* sA = single + (size_t)(mode == 0 ? j : i) * CDIM;
    const float* sB = g_sums + (size_t)(mode == 0 ? i : j) * CDIM;
    const float* xr = src + (size_t)row * CDIM;

    float v[4];
    float mean = 0.f;
#pragma unroll
    for (int q = 0; q < 4; q++) {
        int c = q * 32 + lane;
        v[q] = xr[c] + sA[c] + sB[c];
        mean += v[q];
    }
    mean = warp_sum(mean) * (1.0f / CDIM);
    float var = 0.f;
#pragma unroll
    for (int q = 0; q < 4; q++) { float d = v[q] - mean; var += d * d; }
    var = warp_sum(var) * (1.0f / CDIM);
    float inv = rsqrtf(var + 1e-5f);
    float* orow = out + (size_t)row * CDIM;
#pragma unroll
    for (int q = 0; q < 4; q++) {
        int c = q * 32 + lane;
        orow[c] = (v[q] - mean) * inv * g[c] + b[c];
    }
}

// out = LN(x + y)  (warp per row; y already includes bias)
__global__ __launch_bounds__(256)
void residual_ln_kernel(float* __restrict__ out, const float* __restrict__ x,
                        const float* __restrict__ y,
                        const float* __restrict__ g, const float* __restrict__ b,
                        int nrows) {
    int lane = threadIdx.x & 31, warp = threadIdx.x >> 5;
    int row = blockIdx.x * 8 + warp;
    if (row >= nrows) return;
    const float* xr = x + (size_t)row * CDIM;
    const float* yr = y + (size_t)row * CDIM;
    float v[4];
    float mean = 0.f;
#pragma unroll
    for (int q = 0; q < 4; q++) {
        int c = q * 32 + lane;
        v[q] = xr[c] + yr[c];
        mean += v[q];
    }
    mean = warp_sum(mean) * (1.0f / CDIM);
    float var = 0.f;
#pragma unroll
    for (int q = 0; q < 4; q++) { float d = v[q] - mean; var += d * d; }
    var = warp_sum(var) * (1.0f / CDIM);
    float inv = rsqrtf(var + 1e-5f);
    float* orow = out + (size_t)row * CDIM;
#pragma unroll
    for (int q = 0; q < 4; q++) {
        int c = q * 32 + lane;
        orow[c] = (v[q] - mean) * inv * g[c] + b[c];
    }
}

// ---------------- tiled GEMM: C[M,N] = A[M,K] @ B[K,N] + bias (+optional relu) ----------------
// BM=BN=64, BK=16, 256 threads, 4x4 per thread. M%64==0, N%64==0, K%16==0 (all shapes here).
__global__ __launch_bounds__(256)
void gemm_bias_kernel(const float* __restrict__ A, const float* __restrict__ B,
                      const float* __restrict__ bias, float* __restrict__ C,
                      int M, int N, int K, int relu) {
    __shared__ float As[16][64];
    __shared__ float Bs[16][68];   // pad: 68*4=272B per row, 16B aligned
    int tid = threadIdx.x;
    int tx = tid & 15, ty = tid >> 4;
    int n0 = blockIdx.x * 64, m0 = blockIdx.y * 64;
    float acc[4][4] = {};

    for (int k0 = 0; k0 < K; k0 += 16) {
        {   // A tile: 64x16
            int r = tid >> 2, kq = (tid & 3) << 2;
            float4 a4 = *(const float4*)&A[(size_t)(m0 + r) * K + k0 + kq];
            As[kq + 0][r] = a4.x; As[kq + 1][r] = a4.y;
            As[kq + 2][r] = a4.z; As[kq + 3][r] = a4.w;
        }
        {   // B tile: 16x64
            int r = tid >> 4, nq = (tid & 15) << 2;
            *(float4*)&Bs[r][nq] = *(const float4*)&B[(size_t)(k0 + r) * N + n0 + nq];
        }
        __syncthreads();
#pragma unroll
        for (int kk = 0; kk < 16; kk++) {
            float a[4], bb[4];
#pragma unroll
            for (int i2 = 0; i2 < 4; i2++) a[i2] = As[kk][ty * 4 + i2];
#pragma unroll
            for (int j2 = 0; j2 < 4; j2++) bb[j2] = Bs[kk][tx * 4 + j2];
#pragma unroll
            for (int i2 = 0; i2 < 4; i2++)
#pragma unroll
                for (int j2 = 0; j2 < 4; j2++)
                    acc[i2][j2] += a[i2] * bb[j2];
        }
        __syncthreads();
    }
#pragma unroll
    for (int i2 = 0; i2 < 4; i2++) {
        int mrow = m0 + ty * 4 + i2;
#pragma unroll
        for (int j2 = 0; j2 < 4; j2++) {
            int ncol = n0 + tx * 4 + j2;
            float v = acc[i2][j2] + bias[ncol];
            if (relu) v = fmaxf(v, 0.f);
            C[(size_t)mrow * N + ncol] = v;
        }
    }
}

// ---------------- attention: one block per (i,h), warp per query j ----------------
// scores[j,k] = q[i,j,h]·k[i,k,h]/sqrt(d) + dscale*dist[j,k]; mask -> -inf; softmax over k; AV.
__global__ __launch_bounds__(256)
void attn_kernel(const float* __restrict__ qkv, const float* __restrict__ dist,
                 const float* __restrict__ dscale, float* __restrict__ out,
                 int transposed_mask) {
    extern __shared__ float sh[];
    float* k_sh = sh;                 // [256][33] padded
    float* v_sh = sh + 256 * 33;      // [256][32]
    int ih = blockIdx.x;
    int i = ih >> 2, h = ih & 3;
    int tid = threadIdx.x, lane = tid & 31, warp = tid >> 5;
    float dsc = dscale[0];
    const float* base = qkv + (size_t)i * NSEQ * (3 * CDIM);

    for (int idx = tid; idx < 256 * 32; idx += 256) {
        int r = idx >> 5, d = idx & 31;
        k_sh[r * 33 + d] = base[(size_t)r * 384 + CDIM + h * DHEAD + d];
        v_sh[r * 32 + d] = base[(size_t)r * 384 + 2 * CDIM + h * DHEAD + d];
    }
    __syncthreads();

    const float scale = 0.17677669529663687f;  // 1/sqrt(32)
    for (int jt = 0; jt < 32; jt++) {
        int j = warp * 32 + jt;
        float qv = base[(size_t)j * 384 + h * DHEAD + lane];

        float s[8];
#pragma unroll
        for (int m = 0; m < 8; m++) s[m] = 0.f;
#pragma unroll
        for (int d = 0; d < 32; d++) {
            float qd = __shfl_sync(0xffffffffu, qv, d);
#pragma unroll
            for (int m = 0; m < 8; m++)
                s[m] += qd * k_sh[(lane + 32 * m) * 33 + d];
        }
        float mx = -1e30f;
#pragma unroll
        for (int m = 0; m < 8; m++) {
            int k = lane + 32 * m;
            float sc = s[m] * scale + dsc * __ldg(&dist[(size_t)j * NSEQ + k]);
            unsigned char mk = transposed_mask ? g_mask[(size_t)k * NSEQ + j]
                                               : g_mask[(size_t)j * NSEQ + k];
            sc = mk ? -1e30f : sc;
            s[m] = sc;
            mx = fmaxf(mx, sc);
        }
        mx = warp_max(mx);
        float sum = 0.f;
#pragma unroll
        for (int m = 0; m < 8; m++) { s[m] = expf(s[m] - mx); sum += s[m]; }
        sum = warp_sum(sum);
        float inv = 1.0f / sum;

        float o_acc = 0.f;
#pragma unroll
        for (int m = 0; m < 8; m++) {
#pragma unroll
            for (int src = 0; src < 32; src++) {
                float wk = __shfl_sync(0xffffffffu, s[m], src);
                o_acc += wk * v_sh[(32 * m + src) * 32 + lane];
            }
        }
        out[((size_t)i * NSEQ + j) * CDIM + h * DHEAD + lane] = o_acc * inv;
    }
}

// ---------------- launch ----------------
extern "C" void kernel_launch(void* const* d_in, const int* in_sizes, int n_in,
                              void* d_out, int out_size) {
    const float* pair      = (const float*)d_in[0];
    const float* single    = (const float*)d_in[1];
    const unsigned char* mask = (const unsigned char*)d_in[2];
    const float* dist      = (const float*)d_in[3];
    const float* row_Wqkv  = (const float*)d_in[4];
    const float* row_bqkv  = (const float*)d_in[5];
    const float* row_Wo    = (const float*)d_in[6];
    const float* row_bo    = (const float*)d_in[7];
    const float* row_dsc   = (const float*)d_in[8];
    const float* col_Wqkv  = (const float*)d_in[9];
    const float* col_bqkv  = (const float*)d_in[10];
    const float* col_Wo    = (const float*)d_in[11];
    const float* col_bo    = (const float*)d_in[12];
    const float* col_dsc   = (const float*)d_in[13];
    const float* pnr_g     = (const float*)d_in[14];
    const float* pnr_b     = (const float*)d_in[15];
    const float* pnc_g     = (const float*)d_in[16];
    const float* pnc_b     = (const float*)d_in[17];
    const float* sn_g      = (const float*)d_in[18];
    const float* sn_b      = (const float*)d_in[19];
    const float* W1        = (const float*)d_in[20];
    const float* b1        = (const float*)d_in[21];
    const float* W2        = (const float*)d_in[22];
    const float* b2        = (const float*)d_in[23];

    float* pr = (float*)d_out;                               // [256,256,128]
    float* sr = pr + (size_t)NROWS * CDIM;                   // [256,128]

    float *qkv_p, *attn_p, *h1_p, *h2_p;
    cudaGetSymbolAddress((void**)&qkv_p, g_qkv);
    cudaGetSymbolAddress((void**)&attn_p, g_attn);
    cudaGetSymbolAddress((void**)&h1_p, g_h1);
    cudaGetSymbolAddress((void**)&h2_p, g_h2);
    float* proj_p = qkv_p;   // reuse qkv scratch for out-proj result

    const int ATTN_SMEM = (256 * 33 + 256 * 32) * 4;
    cudaFuncSetAttribute(attn_kernel, cudaFuncAttributeMaxDynamicSharedMemorySize, ATTN_SMEM);

    // mask normalization (deterministic layout detection)
    mask_norm_kernel<<<1, 1024>>>(mask);

    // ---- stage 1: pr = LN(pair + tri_update_out(pair, single)) ----
    rowsum_kernel<<<NSEQ, CDIM>>>(pair);
    trimix_ln_kernel<<<NROWS / 8, 256>>>(pr, pair, single, pnr_g, pnr_b, 0);

    // ---- stage 2: pr = LN(pr + row_attn(pr)) ----
    gemm_bias_kernel<<<dim3(6, 1024), 256>>>(pr, row_Wqkv, row_bqkv, qkv_p, NROWS, 384, 128, 0);
    attn_kernel<<<NSEQ * NHEAD, 256, ATTN_SMEM>>>(qkv_p, dist, row_dsc, attn_p, 0);
    gemm_bias_kernel<<<dim3(2, 1024), 256>>>(attn_p, row_Wo, row_bo, proj_p, NROWS, 128, 128, 0);
    residual_ln_kernel<<<NROWS / 8, 256>>>(pr, pr, proj_p, pnr_g, pnr_b, NROWS);

    // ---- stage 3: pr = LN(pr + tri_update_in(pr, single)) ----
    colsum_kernel<<<NSEQ, CDIM>>>(pr);
    trimix_ln_kernel<<<NROWS / 8, 256>>>(pr, pr, single, pnc_g, pnc_b, 1);

    // ---- stage 4: pr = LN(pr + col_attn(pr)) ----
    gemm_bias_kernel<<<dim3(6, 1024), 256>>>(pr, col_Wqkv, col_bqkv, qkv_p, NROWS, 384, 128, 0);
    attn_kernel<<<NSEQ * NHEAD, 256, ATTN_SMEM>>>(qkv_p, dist, col_dsc, attn_p, 1);
    gemm_bias_kernel<<<dim3(2, 1024), 256>>>(attn_p, col_Wo, col_bo, proj_p, NROWS, 128, 128, 0);
    residual_ln_kernel<<<NROWS / 8, 256>>>(pr, pr, proj_p, pnc_g, pnc_b, NROWS);

    // ---- single-rep MLP + LN ----
    gemm_bias_kernel<<<dim3(4, 4), 256>>>(single, W1, b1, h1_p, NSEQ, 256, 128, 1);
    gemm_bias_kernel<<<dim3(2, 4), 256>>>(h1_p, W2, b2, h2_p, NSEQ, 128, 256, 1);
    residual_ln_kernel<<<NSEQ / 8, 256>>>(sr, single, h2_p, sn_g, sn_b, NSEQ);
}

// round 5
// speedup vs baseline: 1.2359x; 1.2359x over previous
#include <cuda_runtime.h>
#include <math.h>

#define NSEQ 256
#define CDIM 128
#define NHEAD 4
#define DHEAD 32
#define NROWS (NSEQ * NSEQ)

// ---------------- scratch (device globals; no allocation allowed) ----------------
__device__ float g_qkv[(size_t)NROWS * 3 * CDIM];   // 96 MB; also reused as proj output
__device__ float g_attn[(size_t)NROWS * CDIM];      // 32 MB
__device__ float g_sums[NSEQ * CDIM];               // row/col prefix sums
__device__ float g_h1[NSEQ * 2 * CDIM];
__device__ float g_h2[NSEQ * CDIM];
__device__ unsigned char g_mask[NSEQ * NSEQ];
__device__ unsigned char g_maskT[NSEQ * NSEQ];

// ---------------- helpers ----------------
__device__ __forceinline__ float warp_sum(float v) {
#pragma unroll
    for (int o = 16; o; o >>= 1) v += __shfl_xor_sync(0xffffffffu, v, o);
    return v;
}
__device__ __forceinline__ float warp_max(float v) {
#pragma unroll
    for (int o = 16; o; o >>= 1) v = fmaxf(v, __shfl_xor_sync(0xffffffffu, v, o));
    return v;
}

// ---------------- mask normalization (bool-bytes vs int32 ambiguity) ----------------
__global__ void mask_norm_kernel(const unsigned char* __restrict__ m) {
    __shared__ int flag;
    int tid = threadIdx.x;
    if (tid == 0) flag = 0;
    __syncthreads();
    int local = 0;
    for (int idx = tid; idx < NSEQ * NSEQ; idx += blockDim.x)
        if ((idx & 3) && m[idx]) local = 1;
    if (local) atomicOr(&flag, 1);
    __syncthreads();
    int isBytes = flag;
    for (int idx = tid; idx < NSEQ * NSEQ; idx += blockDim.x) {
        g_mask[idx] = isBytes ? m[idx] : m[4 * (size_t)idx];
        int t = (idx & 255) * 256 + (idx >> 8);   // transposed source index
        g_maskT[idx] = isBytes ? m[t] : m[4 * (size_t)t];
    }
}

// ---------------- prefix sums ----------------
__global__ void rowsum_kernel(const float* __restrict__ pair) {
    int i = blockIdx.x, c = threadIdx.x;
    const float* p = pair + (size_t)i * NSEQ * CDIM + c;
    float s = 0.f;
#pragma unroll 4
    for (int k = 0; k < i; k++) s += __ldg(&p[(size_t)k * CDIM]);
    g_sums[i * CDIM + c] = s;
}

__global__ void colsum_kernel(const float* __restrict__ pr) {
    int j = blockIdx.x, c = threadIdx.x;
    const float* p = pr + (size_t)j * CDIM + c;
    float s = 0.f;
#pragma unroll 4
    for (int k = 0; k < j; k++) s += __ldg(&p[(size_t)k * NSEQ * CDIM]);
    g_sums[j * CDIM + c] = s;
}

// ---------------- fused tri-update + LayerNorm (warp per (i,j) row) ----------------
__global__ __launch_bounds__(256)
void trimix_ln_kernel(float* __restrict__ out, const float* __restrict__ src,
                      const float* __restrict__ single,
                      const float* __restrict__ g, const float* __restrict__ b,
                      int mode) {
    int lane = threadIdx.x & 31, warp = threadIdx.x >> 5;
    int row = blockIdx.x * 8 + warp;
    int i = row >> 8, j = row & 255;
    const float* sA = single + (size_t)(mode == 0 ? j : i) * CDIM;
    const float* sB = g_sums + (size_t)(mode == 0 ? i : j) * CDIM;
    const float* xr = src + (size_t)row * CDIM;

    float v[4];
    float mean = 0.f;
#pragma unroll
    for (int q = 0; q < 4; q++) {
        int c = q * 32 + lane;
        v[q] = xr[c] + sA[c] + sB[c];
        mean += v[q];
    }
    mean = warp_sum(mean) * (1.0f / CDIM);
    float var = 0.f;
#pragma unroll
    for (int q = 0; q < 4; q++) { float d = v[q] - mean; var += d * d; }
    var = warp_sum(var) * (1.0f / CDIM);
    float inv = rsqrtf(var + 1e-5f);
    float* orow = out + (size_t)row * CDIM;
#pragma unroll
    for (int q = 0; q < 4; q++) {
        int c = q * 32 + lane;
        orow[c] = (v[q] - mean) * inv * g[c] + b[c];
    }
}

__global__ __launch_bounds__(256)
void residual_ln_kernel(float* __restrict__ out, const float* __restrict__ x,
                        const float* __restrict__ y,
                        const float* __restrict__ g, const float* __restrict__ b,
                        int nrows) {
    int lane = threadIdx.x & 31, warp = threadIdx.x >> 5;
    int row = blockIdx.x * 8 + warp;
    if (row >= nrows) return;
    const float* xr = x + (size_t)row * CDIM;
    const float* yr = y + (size_t)row * CDIM;
    float v[4];
    float mean = 0.f;
#pragma unroll
    for (int q = 0; q < 4; q++) {
        int c = q * 32 + lane;
        v[q] = xr[c] + yr[c];
        mean += v[q];
    }
    mean = warp_sum(mean) * (1.0f / CDIM);
    float var = 0.f;
#pragma unroll
    for (int q = 0; q < 4; q++) { float d = v[q] - mean; var += d * d; }
    var = warp_sum(var) * (1.0f / CDIM);
    float inv = rsqrtf(var + 1e-5f);
    float* orow = out + (size_t)row * CDIM;
#pragma unroll
    for (int q = 0; q < 4; q++) {
        int c = q * 32 + lane;
        orow[c] = (v[q] - mean) * inv * g[c] + b[c];
    }
}

// ---------------- SGEMM 128x128x16, 8x8 per thread ----------------
// C[M,N] = A[M,K] @ B[K,N] + bias (+relu). M%128==0, N%128==0, K%16==0.
__global__ __launch_bounds__(256)
void gemm128_kernel(const float* __restrict__ A, const float* __restrict__ B,
                    const float* __restrict__ bias, float* __restrict__ C,
                    int M, int N, int K, int relu) {
    __shared__ float As[16][128];
    __shared__ float Bs[16][132];
    int tid = threadIdx.x;
    int m0 = blockIdx.y * 128, n0 = blockIdx.x * 128;
    int tx = tid & 15, ty = tid >> 4;
    int arow = tid >> 1, acolg = (tid & 1) << 3;
    int brow = tid >> 5, bcol = (tid & 31) << 2;
    float acc[8][8] = {};
    const float* Aptr = A + (size_t)(m0 + arow) * K;

    for (int k0 = 0; k0 < K; k0 += 16) {
        float4 a0 = *(const float4*)&Aptr[k0 + acolg];
        float4 a1 = *(const float4*)&Aptr[k0 + acolg + 4];
        As[acolg + 0][arow] = a0.x; As[acolg + 1][arow] = a0.y;
        As[acolg + 2][arow] = a0.z; As[acolg + 3][arow] = a0.w;
        As[acolg + 4][arow] = a1.x; As[acolg + 5][arow] = a1.y;
        As[acolg + 6][arow] = a1.z; As[acolg + 7][arow] = a1.w;
        float4 b0 = *(const float4*)&B[(size_t)(k0 + brow) * N + n0 + bcol];
        float4 b1 = *(const float4*)&B[(size_t)(k0 + brow + 8) * N + n0 + bcol];
        *(float4*)&Bs[brow][bcol] = b0;
        *(float4*)&Bs[brow + 8][bcol] = b1;
        __syncthreads();
#pragma unroll
        for (int kk = 0; kk < 16; kk++) {
            float a[8], b[8];
            *(float4*)(a)     = *(const float4*)&As[kk][ty * 8];
            *(float4*)(a + 4) = *(const float4*)&As[kk][ty * 8 + 4];
            *(float4*)(b)     = *(const float4*)&Bs[kk][tx * 8];
            *(float4*)(b + 4) = *(const float4*)&Bs[kk][tx * 8 + 4];
#pragma unroll
            for (int i2 = 0; i2 < 8; i2++)
#pragma unroll
                for (int j2 = 0; j2 < 8; j2++)
                    acc[i2][j2] += a[i2] * b[j2];
        }
        __syncthreads();
    }

    float4 bi0 = *(const float4*)&bias[n0 + tx * 8];
    float4 bi1 = *(const float4*)&bias[n0 + tx * 8 + 4];
#pragma unroll
    for (int r = 0; r < 8; r++) {
        float* crow = C + (size_t)(m0 + ty * 8 + r) * N + n0 + tx * 8;
        float4 o0 = make_float4(acc[r][0] + bi0.x, acc[r][1] + bi0.y,
                                acc[r][2] + bi0.z, acc[r][3] + bi0.w);
        float4 o1 = make_float4(acc[r][4] + bi1.x, acc[r][5] + bi1.y,
                                acc[r][6] + bi1.z, acc[r][7] + bi1.w);
        if (relu) {
            o0.x = fmaxf(o0.x, 0.f); o0.y = fmaxf(o0.y, 0.f);
            o0.z = fmaxf(o0.z, 0.f); o0.w = fmaxf(o0.w, 0.f);
            o1.x = fmaxf(o1.x, 0.f); o1.y = fmaxf(o1.y, 0.f);
            o1.z = fmaxf(o1.z, 0.f); o1.w = fmaxf(o1.w, 0.f);
        }
        *(float4*)crow = o0;
        *(float4*)(crow + 4) = o1;
    }
}

// ---------------- tiled attention: block per (jt, h, i), 64 j-rows per block ----------------
// smem layout (floats): Qs[32][68] | Ks[32][260] | Vs[256][33] | S[64][256]
#define ATT_QS 0
#define ATT_KS 2176
#define ATT_VS (ATT_KS + 8320)
#define ATT_S  (ATT_VS + 8448)
#define ATT_FLOATS (ATT_S + 64 * 256)
#define ATT_SMEM_BYTES (ATT_FLOATS * 4)

__global__ __launch_bounds__(256)
void attn_tile_kernel(const float* __restrict__ qkv, const float* __restrict__ dist,
                      const float* __restrict__ dscale,
                      const unsigned char* __restrict__ maskp,
                      float* __restrict__ out) {
    extern __shared__ float sh[];
    float* Qs = sh + ATT_QS;   // [32][68]  Q^T tile
    float* Ks = sh + ATT_KS;   // [32][260] K^T
    float* Vs = sh + ATT_VS;   // [256][33]
    float* S  = sh + ATT_S;    // [64][256]
    int jt = blockIdx.x, h = blockIdx.y, i = blockIdx.z;
    int tid = threadIdx.x, lane = tid & 31, w = tid >> 5;
    const float* base = qkv + (size_t)i * NSEQ * 384;

    for (int idx = tid; idx < 64 * 32; idx += 256) {
        int j = idx >> 5, d = idx & 31;
        Qs[d * 68 + j] = base[(size_t)(jt * 64 + j) * 384 + h * 32 + d];
    }
    for (int idx = tid; idx < 256 * 32; idx += 256) {
        int k = idx >> 5, d = idx & 31;
        Ks[d * 260 + k] = base[(size_t)k * 384 + 128 + h * 32 + d];
    }
    for (int idx = tid; idx < 256 * 32; idx += 256) {
        int k = idx >> 5, d = idx & 31;
        Vs[k * 33 + d] = base[(size_t)k * 384 + 256 + h * 32 + d];
    }
    __syncthreads();

    const float dsc = dscale[0];
    const float scale = 0.17677669529663687f;  // 1/sqrt(32)

    // ---- QK^T: warp w owns rows w*8..w*8+7; thread owns cols lane*8..lane*8+7 ----
    float acc[8][8];
#pragma unroll
    for (int r = 0; r < 8; r++)
#pragma unroll
        for (int c = 0; c < 8; c++) acc[r][c] = 0.f;

#pragma unroll 4
    for (int d = 0; d < 32; d++) {
        float qr[8], kr[8];
        *(float4*)(qr)     = *(const float4*)&Qs[d * 68 + w * 8];
        *(float4*)(qr + 4) = *(const float4*)&Qs[d * 68 + w * 8 + 4];
        *(float4*)(kr)     = *(const float4*)&Ks[d * 260 + lane * 8];
        *(float4*)(kr + 4) = *(const float4*)&Ks[d * 260 + lane * 8 + 4];
#pragma unroll
        for (int r = 0; r < 8; r++)
#pragma unroll
            for (int c = 0; c < 8; c++)
                acc[r][c] += qr[r] * kr[c];
    }

    int jrow0 = jt * 64 + w * 8;
#pragma unroll
    for (int r = 0; r < 8; r++) {
        int jg = jrow0 + r;
        const float* drow = dist + (size_t)jg * 256 + lane * 8;
        float4 d0 = *(const float4*)drow;
        float4 d1 = *(const float4*)(drow + 4);
        uchar4 mk0 = *(const uchar4*)&maskp[(size_t)jg * 256 + lane * 8];
        uchar4 mk1 = *(const uchar4*)&maskp[(size_t)jg * 256 + lane * 8 + 4];
        float4 s0, s1;
        s0.x = mk0.x ? -1e30f : fmaf(acc[r][0], scale, dsc * d0.x);
        s0.y = mk0.y ? -1e30f : fmaf(acc[r][1], scale, dsc * d0.y);
        s0.z = mk0.z ? -1e30f : fmaf(acc[r][2], scale, dsc * d0.z);
        s0.w = mk0.w ? -1e30f : fmaf(acc[r][3], scale, dsc * d0.w);
        s1.x = mk1.x ? -1e30f : fmaf(acc[r][4], scale, dsc * d1.x);
        s1.y = mk1.y ? -1e30f : fmaf(acc[r][5], scale, dsc * d1.y);
        s1.z = mk1.z ? -1e30f : fmaf(acc[r][6], scale, dsc * d1.z);
        s1.w = mk1.w ? -1e30f : fmaf(acc[r][7], scale, dsc * d1.w);
        *(float4*)&S[(w * 8 + r) * 256 + lane * 8] = s0;
        *(float4*)&S[(w * 8 + r) * 256 + lane * 8 + 4] = s1;
    }
    __syncwarp();

    // ---- softmax over each of this warp's 8 rows ----
#pragma unroll
    for (int r = 0; r < 8; r++) {
        float* row = S + (w * 8 + r) * 256;
        float v[8];
        *(float4*)(v)     = *(const float4*)&row[lane * 8];
        *(float4*)(v + 4) = *(const float4*)&row[lane * 8 + 4];
        float mx = v[0];
#pragma unroll
        for (int q = 1; q < 8; q++) mx = fmaxf(mx, v[q]);
        mx = warp_max(mx);
        float sum = 0.f;
#pragma unroll
        for (int q = 0; q < 8; q++) { v[q] = __expf(v[q] - mx); sum += v[q]; }
        sum = warp_sum(sum);
        float inv = 1.0f / sum;
#pragma unroll
        for (int q = 0; q < 8; q++) v[q] *= inv;
        *(float4*)&row[lane * 8]     = *(float4*)(v);
        *(float4*)&row[lane * 8 + 4] = *(float4*)(v + 4);
    }
    __syncwarp();

    // ---- AV: out rows w*8..w*8+7, d = lane ----
    float o[8] = {};
    for (int k0 = 0; k0 < 256; k0 += 4) {
        float v0 = Vs[(k0 + 0) * 33 + lane];
        float v1 = Vs[(k0 + 1) * 33 + lane];
        float v2 = Vs[(k0 + 2) * 33 + lane];
        float v3 = Vs[(k0 + 3) * 33 + lane];
#pragma unroll
        for (int r = 0; r < 8; r++) {
            float4 wv = *(const float4*)&S[(w * 8 + r) * 256 + k0];
            o[r] += wv.x * v0 + wv.y * v1 + wv.z * v2 + wv.w * v3;
        }
    }
#pragma unroll
    for (int r = 0; r < 8; r++)
        out[((size_t)i * NSEQ + jrow0 + r) * CDIM + h * 32 + lane] = o[r];
}

// ---------------- launch ----------------
extern "C" void kernel_launch(void* const* d_in, const int* in_sizes, int n_in,
                              void* d_out, int out_size) {
    const float* pair      = (const float*)d_in[0];
    const float* single    = (const float*)d_in[1];
    const unsigned char* mask = (const unsigned char*)d_in[2];
    const float* dist      = (const float*)d_in[3];
    const float* row_Wqkv  = (const float*)d_in[4];
    const float* row_bqkv  = (const float*)d_in[5];
    const float* row_Wo    = (const float*)d_in[6];
    const float* row_bo    = (const float*)d_in[7];
    const float* row_dsc   = (const float*)d_in[8];
    const float* col_Wqkv  = (const float*)d_in[9];
    const float* col_bqkv  = (const float*)d_in[10];
    const float* col_Wo    = (const float*)d_in[11];
    const float* col_bo    = (const float*)d_in[12];
    const float* col_dsc   = (const float*)d_in[13];
    const float* pnr_g     = (const float*)d_in[14];
    const float* pnr_b     = (const float*)d_in[15];
    const float* pnc_g     = (const float*)d_in[16];
    const float* pnc_b     = (const float*)d_in[17];
    const float* sn_g      = (const float*)d_in[18];
    const float* sn_b      = (const float*)d_in[19];
    const float* W1        = (const float*)d_in[20];
    const float* b1        = (const float*)d_in[21];
    const float* W2        = (const float*)d_in[22];
    const float* b2        = (const float*)d_in[23];

    float* pr = (float*)d_out;                               // [256,256,128]
    float* sr = pr + (size_t)NROWS * CDIM;                   // [256,128]

    float *qkv_p, *attn_p, *h1_p, *h2_p;
    unsigned char *mask_p, *maskT_p;
    cudaGetSymbolAddress((void**)&qkv_p, g_qkv);
    cudaGetSymbolAddress((void**)&attn_p, g_attn);
    cudaGetSymbolAddress((void**)&h1_p, g_h1);
    cudaGetSymbolAddress((void**)&h2_p, g_h2);
    cudaGetSymbolAddress((void**)&mask_p, g_mask);
    cudaGetSymbolAddress((void**)&maskT_p, g_maskT);
    float* proj_p = qkv_p;   // reuse qkv scratch for out-proj result

    cudaFuncSetAttribute(attn_tile_kernel, cudaFuncAttributeMaxDynamicSharedMemorySize,
                         ATT_SMEM_BYTES);

    // mask normalization + transpose
    mask_norm_kernel<<<1, 1024>>>(mask);

    // ---- stage 1: pr = LN(pair + tri_update_out(pair, single)) ----
    rowsum_kernel<<<NSEQ, CDIM>>>(pair);
    trimix_ln_kernel<<<NROWS / 8, 256>>>(pr, pair, single, pnr_g, pnr_b, 0);

    // ---- stage 2: pr = LN(pr + row_attn(pr)) ----
    gemm128_kernel<<<dim3(3, 512), 256>>>(pr, row_Wqkv, row_bqkv, qkv_p, NROWS, 384, 128, 0);
    attn_tile_kernel<<<dim3(4, NHEAD, NSEQ), 256, ATT_SMEM_BYTES>>>(qkv_p, dist, row_dsc, mask_p, attn_p);
    gemm128_kernel<<<dim3(1, 512), 256>>>(attn_p, row_Wo, row_bo, proj_p, NROWS, 128, 128, 0);
    residual_ln_kernel<<<NROWS / 8, 256>>>(pr, pr, proj_p, pnr_g, pnr_b, NROWS);

    // ---- stage 3: pr = LN(pr + tri_update_in(pr, single)) ----
    colsum_kernel<<<NSEQ, CDIM>>>(pr);
    trimix_ln_kernel<<<NROWS / 8, 256>>>(pr, pr, single, pnc_g, pnc_b, 1);

    // ---- stage 4: pr = LN(pr + col_attn(pr)) ----
    gemm128_kernel<<<dim3(3, 512), 256>>>(pr, col_Wqkv, col_bqkv, qkv_p, NROWS, 384, 128, 0);
    attn_tile_kernel<<<dim3(4, NHEAD, NSEQ), 256, ATT_SMEM_BYTES>>>(qkv_p, dist, col_dsc, maskT_p, attn_p);
    gemm128_kernel<<<dim3(1, 512), 256>>>(attn_p, col_Wo, col_bo, proj_p, NROWS, 128, 128, 0);
    residual_ln_kernel<<<NROWS / 8, 256>>>(pr, pr, proj_p, pnc_g, pnc_b, NROWS);

    // ---- single-rep MLP + LN ----
    gemm128_kernel<<<dim3(2, 2), 256>>>(single, W1, b1, h1_p, NSEQ, 256, 128, 1);
    gemm128_kernel<<<dim3(1, 2), 256>>>(h1_p, W2, b2, h2_p, NSEQ, 128, 256, 1);
    residual_ln_kernel<<<NSEQ / 8, 256>>>(sr, single, h2_p, sn_g, sn_b, NSEQ);
}

// round 6
// speedup vs baseline: 1.3762x; 1.1135x over previous
#include <cuda_runtime.h>
#include <math.h>

#define NSEQ 256
#define CDIM 128
#define NHEAD 4
#define DHEAD 32
#define NROWS (NSEQ * NSEQ)

// ---------------- scratch (device globals; no allocation allowed) ----------------
__device__ float g_qkv[(size_t)NROWS * 3 * CDIM];   // 96 MB
__device__ float g_attn[(size_t)NROWS * CDIM];      // 32 MB
__device__ float g_sums[NSEQ * CDIM];               // row/col prefix sums
__device__ float g_h1[NSEQ * 2 * CDIM];
__device__ float g_h2[NSEQ * CDIM];
__device__ float g_bias_row[NSEQ * NSEQ];           // dscale*dist with mask folded
__device__ float g_bias_col[NSEQ * NSEQ];

// ---------------- helpers ----------------
__device__ __forceinline__ float warp_sum(float v) {
#pragma unroll
    for (int o = 16; o; o >>= 1) v += __shfl_xor_sync(0xffffffffu, v, o);
    return v;
}
__device__ __forceinline__ float warp_max(float v) {
#pragma unroll
    for (int o = 16; o; o >>= 1) v = fmaxf(v, __shfl_xor_sync(0xffffffffu, v, o));
    return v;
}
__device__ __forceinline__ float half16_sum(float v) {
#pragma unroll
    for (int o = 8; o; o >>= 1) v += __shfl_xor_sync(0xffffffffu, v, o);
    return v;
}

// ---------------- mask detect + fused bias tables ----------------
// bias_row[j,k] = mask[j,k] ? -1e30 : rdsc*dist[j,k]
// bias_col[j,k] = mask[k,j] ? -1e30 : cdsc*dist[j,k]
__global__ void maskbias_kernel(const unsigned char* __restrict__ m,
                                const float* __restrict__ dist,
                                const float* __restrict__ rdsc,
                                const float* __restrict__ cdsc) {
    __shared__ int flag;
    int tid = threadIdx.x;
    if (tid == 0) flag = 0;
    __syncthreads();
    int local = 0;
    for (int idx = tid; idx < NSEQ * NSEQ; idx += blockDim.x)
        if ((idx & 3) && m[idx]) local = 1;
    if (local) atomicOr(&flag, 1);
    __syncthreads();
    int isBytes = flag;
    float rs = rdsc[0], cs = cdsc[0];
    for (int idx = tid; idx < NSEQ * NSEQ; idx += blockDim.x) {
        int t = (idx & 255) * 256 + (idx >> 8);
        unsigned char mb = isBytes ? m[idx] : m[4 * (size_t)idx];
        unsigned char mt = isBytes ? m[t] : m[4 * (size_t)t];
        float dv = dist[idx];
        g_bias_row[idx] = mb ? -1e30f : rs * dv;
        g_bias_col[idx] = mt ? -1e30f : cs * dv;
    }
}

// ---------------- prefix sums ----------------
__global__ void rowsum_kernel(const float* __restrict__ pair) {
    int i = blockIdx.x, c = threadIdx.x;
    const float* p = pair + (size_t)i * NSEQ * CDIM + c;
    float s = 0.f;
#pragma unroll 4
    for (int k = 0; k < i; k++) s += __ldg(&p[(size_t)k * CDIM]);
    g_sums[i * CDIM + c] = s;
}

__global__ void colsum_kernel(const float* __restrict__ pr) {
    int j = blockIdx.x, c = threadIdx.x;
    const float* p = pr + (size_t)j * CDIM + c;
    float s = 0.f;
#pragma unroll 4
    for (int k = 0; k < j; k++) s += __ldg(&p[(size_t)k * NSEQ * CDIM]);
    g_sums[j * CDIM + c] = s;
}

// ---------------- fused tri-update + LayerNorm (warp per (i,j) row) ----------------
__global__ __launch_bounds__(256)
void trimix_ln_kernel(float* __restrict__ out, const float* __restrict__ src,
                      const float* __restrict__ single,
                      const float* __restrict__ g, const float* __restrict__ b,
                      int mode) {
    int lane = threadIdx.x & 31, warp = threadIdx.x >> 5;
    int row = blockIdx.x * 8 + warp;
    int i = row >> 8, j = row & 255;
    const float* sA = single + (size_t)(mode == 0 ? j : i) * CDIM;
    const float* sB = g_sums + (size_t)(mode == 0 ? i : j) * CDIM;
    const float* xr = src + (size_t)row * CDIM;

    float v[4];
    float mean = 0.f;
#pragma unroll
    for (int q = 0; q < 4; q++) {
        int c = q * 32 + lane;
        v[q] = xr[c] + sA[c] + sB[c];
        mean += v[q];
    }
    mean = warp_sum(mean) * (1.0f / CDIM);
    float var = 0.f;
#pragma unroll
    for (int q = 0; q < 4; q++) { float d = v[q] - mean; var += d * d; }
    var = warp_sum(var) * (1.0f / CDIM);
    float inv = rsqrtf(var + 1e-5f);
    float* orow = out + (size_t)row * CDIM;
#pragma unroll
    for (int q = 0; q < 4; q++) {
        int c = q * 32 + lane;
        orow[c] = (v[q] - mean) * inv * g[c] + b[c];
    }
}

__global__ __launch_bounds__(256)
void residual_ln_kernel(float* __restrict__ out, const float* __restrict__ x,
                        const float* __restrict__ y,
                        const float* __restrict__ g, const float* __restrict__ b,
                        int nrows) {
    int lane = threadIdx.x & 31, warp = threadIdx.x >> 5;
    int row = blockIdx.x * 8 + warp;
    if (row >= nrows) return;
    const float* xr = x + (size_t)row * CDIM;
    const float* yr = y + (size_t)row * CDIM;
    float v[4];
    float mean = 0.f;
#pragma unroll
    for (int q = 0; q < 4; q++) {
        int c = q * 32 + lane;
        v[q] = xr[c] + yr[c];
        mean += v[q];
    }
    mean = warp_sum(mean) * (1.0f / CDIM);
    float var = 0.f;
#pragma unroll
    for (int q = 0; q < 4; q++) { float d = v[q] - mean; var += d * d; }
    var = warp_sum(var) * (1.0f / CDIM);
    float inv = rsqrtf(var + 1e-5f);
    float* orow = out + (size_t)row * CDIM;
#pragma unroll
    for (int q = 0; q < 4; q++) {
        int c = q * 32 + lane;
        orow[c] = (v[q] - mean) * inv * g[c] + b[c];
    }
}

// ---------------- double-buffered SGEMM 128x128x16, 8x8 per thread ----------------
__global__ __launch_bounds__(256)
void gemm128_kernel(const float* __restrict__ A, const float* __restrict__ B,
                    const float* __restrict__ bias, float* __restrict__ C,
                    int M, int N, int K, int relu) {
    __shared__ float As[2][16][128];
    __shared__ float Bs[2][16][132];
    int tid = threadIdx.x;
    int m0 = blockIdx.y * 128, n0 = blockIdx.x * 128;
    int tx = tid & 15, ty = tid >> 4;
    int arow = tid >> 1, acolg = (tid & 1) << 3;
    int brow = tid >> 5, bcol = (tid & 31) << 2;
    const float* Aptr = A + (size_t)(m0 + arow) * K;

    // tile 0
    {
        float4 a0 = *(const float4*)&Aptr[acolg];
        float4 a1 = *(const float4*)&Aptr[acolg + 4];
        As[0][acolg + 0][arow] = a0.x; As[0][acolg + 1][arow] = a0.y;
        As[0][acolg + 2][arow] = a0.z; As[0][acolg + 3][arow] = a0.w;
        As[0][acolg + 4][arow] = a1.x; As[0][acolg + 5][arow] = a1.y;
        As[0][acolg + 6][arow] = a1.z; As[0][acolg + 7][arow] = a1.w;
        *(float4*)&Bs[0][brow][bcol]     = *(const float4*)&B[(size_t)brow * N + n0 + bcol];
        *(float4*)&Bs[0][brow + 8][bcol] = *(const float4*)&B[(size_t)(brow + 8) * N + n0 + bcol];
    }
    __syncthreads();

    float acc[8][8] = {};
    int buf = 0;
    for (int k0 = 16; k0 < K; k0 += 16) {
        float4 na0 = *(const float4*)&Aptr[k0 + acolg];
        float4 na1 = *(const float4*)&Aptr[k0 + acolg + 4];
        float4 nb0 = *(const float4*)&B[(size_t)(k0 + brow) * N + n0 + bcol];
        float4 nb1 = *(const float4*)&B[(size_t)(k0 + brow + 8) * N + n0 + bcol];
#pragma unroll
        for (int kk = 0; kk < 16; kk++) {
            float a[8], b[8];
            *(float4*)(a)     = *(const float4*)&As[buf][kk][ty * 8];
            *(float4*)(a + 4) = *(const float4*)&As[buf][kk][ty * 8 + 4];
            *(float4*)(b)     = *(const float4*)&Bs[buf][kk][tx * 8];
            *(float4*)(b + 4) = *(const float4*)&Bs[buf][kk][tx * 8 + 4];
#pragma unroll
            for (int i2 = 0; i2 < 8; i2++)
#pragma unroll
                for (int j2 = 0; j2 < 8; j2++)
                    acc[i2][j2] += a[i2] * b[j2];
        }
        int nb = buf ^ 1;
        As[nb][acolg + 0][arow] = na0.x; As[nb][acolg + 1][arow] = na0.y;
        As[nb][acolg + 2][arow] = na0.z; As[nb][acolg + 3][arow] = na0.w;
        As[nb][acolg + 4][arow] = na1.x; As[nb][acolg + 5][arow] = na1.y;
        As[nb][acolg + 6][arow] = na1.z; As[nb][acolg + 7][arow] = na1.w;
        *(float4*)&Bs[nb][brow][bcol]     = nb0;
        *(float4*)&Bs[nb][brow + 8][bcol] = nb1;
        __syncthreads();
        buf = nb;
    }
#pragma unroll
    for (int kk = 0; kk < 16; kk++) {
        float a[8], b[8];
        *(float4*)(a)     = *(const float4*)&As[buf][kk][ty * 8];
        *(float4*)(a + 4) = *(const float4*)&As[buf][kk][ty * 8 + 4];
        *(float4*)(b)     = *(const float4*)&Bs[buf][kk][tx * 8];
        *(float4*)(b + 4) = *(const float4*)&Bs[buf][kk][tx * 8 + 4];
#pragma unroll
        for (int i2 = 0; i2 < 8; i2++)
#pragma unroll
            for (int j2 = 0; j2 < 8; j2++)
                acc[i2][j2] += a[i2] * b[j2];
    }

    float4 bi0 = *(const float4*)&bias[n0 + tx * 8];
    float4 bi1 = *(const float4*)&bias[n0 + tx * 8 + 4];
#pragma unroll
    for (int r = 0; r < 8; r++) {
        float* crow = C + (size_t)(m0 + ty * 8 + r) * N + n0 + tx * 8;
        float4 o0 = make_float4(acc[r][0] + bi0.x, acc[r][1] + bi0.y,
                                acc[r][2] + bi0.z, acc[r][3] + bi0.w);
        float4 o1 = make_float4(acc[r][4] + bi1.x, acc[r][5] + bi1.y,
                                acc[r][6] + bi1.z, acc[r][7] + bi1.w);
        if (relu) {
            o0.x = fmaxf(o0.x, 0.f); o0.y = fmaxf(o0.y, 0.f);
            o0.z = fmaxf(o0.z, 0.f); o0.w = fmaxf(o0.w, 0.f);
            o1.x = fmaxf(o1.x, 0.f); o1.y = fmaxf(o1.y, 0.f);
            o1.z = fmaxf(o1.z, 0.f); o1.w = fmaxf(o1.w, 0.f);
        }
        *(float4*)crow = o0;
        *(float4*)(crow + 4) = o1;
    }
}

// ---------------- fused out-proj + residual + LayerNorm (N=K=128) ----------------
// out = LN(xres + A@B + bias). grid.x = M/128. Safe for out==xres.
__global__ __launch_bounds__(256)
void gemm_wo_ln_kernel(const float* __restrict__ A, const float* __restrict__ B,
                       const float* __restrict__ bias, const float* __restrict__ xres,
                       const float* __restrict__ g, const float* __restrict__ bb,
                       float* __restrict__ out) {
    __shared__ float As[2][16][128];
    __shared__ float Bs[2][16][132];
    int tid = threadIdx.x;
    int m0 = blockIdx.x * 128;
    int tx = tid & 15, ty = tid >> 4;
    int arow = tid >> 1, acolg = (tid & 1) << 3;
    int brow = tid >> 5, bcol = (tid & 31) << 2;
    const float* Aptr = A + (size_t)(m0 + arow) * 128;

    {
        float4 a0 = *(const float4*)&Aptr[acolg];
        float4 a1 = *(const float4*)&Aptr[acolg + 4];
        As[0][acolg + 0][arow] = a0.x; As[0][acolg + 1][arow] = a0.y;
        As[0][acolg + 2][arow] = a0.z; As[0][acolg + 3][arow] = a0.w;
        As[0][acolg + 4][arow] = a1.x; As[0][acolg + 5][arow] = a1.y;
        As[0][acolg + 6][arow] = a1.z; As[0][acolg + 7][arow] = a1.w;
        *(float4*)&Bs[0][brow][bcol]     = *(const float4*)&B[(size_t)brow * 128 + bcol];
        *(float4*)&Bs[0][brow + 8][bcol] = *(const float4*)&B[(size_t)(brow + 8) * 128 + bcol];
    }
    __syncthreads();

    float acc[8][8] = {};
    int buf = 0;
    for (int k0 = 16; k0 < 128; k0 += 16) {
        float4 na0 = *(const float4*)&Aptr[k0 + acolg];
        float4 na1 = *(const float4*)&Aptr[k0 + acolg + 4];
        float4 nb0 = *(const float4*)&B[(size_t)(k0 + brow) * 128 + bcol];
        float4 nb1 = *(const float4*)&B[(size_t)(k0 + brow + 8) * 128 + bcol];
#pragma unroll
        for (int kk = 0; kk < 16; kk++) {
            float a[8], b[8];
            *(float4*)(a)     = *(const float4*)&As[buf][kk][ty * 8];
            *(float4*)(a + 4) = *(const float4*)&As[buf][kk][ty * 8 + 4];
            *(float4*)(b)     = *(const float4*)&Bs[buf][kk][tx * 8];
            *(float4*)(b + 4) = *(const float4*)&Bs[buf][kk][tx * 8 + 4];
#pragma unroll
            for (int i2 = 0; i2 < 8; i2++)
#pragma unroll
                for (int j2 = 0; j2 < 8; j2++)
                    acc[i2][j2] += a[i2] * b[j2];
        }
        int nb = buf ^ 1;
        As[nb][acolg + 0][arow] = na0.x; As[nb][acolg + 1][arow] = na0.y;
        As[nb][acolg + 2][arow] = na0.z; As[nb][acolg + 3][arow] = na0.w;
        As[nb][acolg + 4][arow] = na1.x; As[nb][acolg + 5][arow] = na1.y;
        As[nb][acolg + 6][arow] = na1.z; As[nb][acolg + 7][arow] = na1.w;
        *(float4*)&Bs[nb][brow][bcol]     = nb0;
        *(float4*)&Bs[nb][brow + 8][bcol] = nb1;
        __syncthreads();
        buf = nb;
    }
#pragma unroll
    for (int kk = 0; kk < 16; kk++) {
        float a[8], b[8];
        *(float4*)(a)     = *(const float4*)&As[buf][kk][ty * 8];
        *(float4*)(a + 4) = *(const float4*)&As[buf][kk][ty * 8 + 4];
        *(float4*)(b)     = *(const float4*)&Bs[buf][kk][tx * 8];
        *(float4*)(b + 4) = *(const float4*)&Bs[buf][kk][tx * 8 + 4];
#pragma unroll
        for (int i2 = 0; i2 < 8; i2++)
#pragma unroll
            for (int j2 = 0; j2 < 8; j2++)
                acc[i2][j2] += a[i2] * b[j2];
    }

    // epilogue: residual + LN per row (each row owned by 16 tx-threads)
    float4 bi0 = *(const float4*)&bias[tx * 8];
    float4 bi1 = *(const float4*)&bias[tx * 8 + 4];
    float4 g0  = *(const float4*)&g[tx * 8];
    float4 g1  = *(const float4*)&g[tx * 8 + 4];
    float4 be0 = *(const float4*)&bb[tx * 8];
    float4 be1 = *(const float4*)&bb[tx * 8 + 4];
#pragma unroll
    for (int r = 0; r < 8; r++) {
        int row = m0 + ty * 8 + r;
        const float* xr = xres + (size_t)row * 128 + tx * 8;
        float4 x0 = *(const float4*)xr;
        float4 x1 = *(const float4*)(xr + 4);
        float v[8];
        v[0] = acc[r][0] + bi0.x + x0.x; v[1] = acc[r][1] + bi0.y + x0.y;
        v[2] = acc[r][2] + bi0.z + x0.z; v[3] = acc[r][3] + bi0.w + x0.w;
        v[4] = acc[r][4] + bi1.x + x1.x; v[5] = acc[r][5] + bi1.y + x1.y;
        v[6] = acc[r][6] + bi1.z + x1.z; v[7] = acc[r][7] + bi1.w + x1.w;
        float s = 0.f;
#pragma unroll
        for (int q = 0; q < 8; q++) s += v[q];
        s = half16_sum(s);
        float mean = s * (1.0f / 128.0f);
        float d2 = 0.f;
#pragma unroll
        for (int q = 0; q < 8; q++) { float d = v[q] - mean; d2 += d * d; }
        d2 = half16_sum(d2);
        float inv = rsqrtf(d2 * (1.0f / 128.0f) + 1e-5f);
        float* orow = out + (size_t)row * 128 + tx * 8;
        float4 o0, o1;
        o0.x = (v[0] - mean) * inv * g0.x + be0.x;
        o0.y = (v[1] - mean) * inv * g0.y + be0.y;
        o0.z = (v[2] - mean) * inv * g0.z + be0.z;
        o0.w = (v[3] - mean) * inv * g0.w + be0.w;
        o1.x = (v[4] - mean) * inv * g1.x + be1.x;
        o1.y = (v[5] - mean) * inv * g1.y + be1.y;
        o1.z = (v[6] - mean) * inv * g1.z + be1.z;
        o1.w = (v[7] - mean) * inv * g1.w + be1.w;
        *(float4*)orow = o0;
        *(float4*)(orow + 4) = o1;
    }
}

// ---------------- tiled attention: block per (jt, h, i), 64 j-rows per block ----------------
// smem floats: Qs[32][68] | Ks[32][260] | VsT[32][264] | S[64][256]
#define ATT_QS 0
#define ATT_KS 2176
#define ATT_VT (ATT_KS + 32 * 260)
#define ATT_S  (ATT_VT + 32 * 264)
#define ATT_FLOATS (ATT_S + 64 * 256)
#define ATT_SMEM_BYTES (ATT_FLOATS * 4)

__global__ __launch_bounds__(256)
void attn_tile_kernel(const float* __restrict__ qkv, const float* __restrict__ biasmat,
                      float* __restrict__ out) {
    extern __shared__ float sh[];
    float* Qs  = sh + ATT_QS;   // Q^T [d][j]
    float* Ks  = sh + ATT_KS;   // K^T [d][k]
    float* VsT = sh + ATT_VT;   // V^T [d][k], row stride 264
    float* S   = sh + ATT_S;    // weights [j][k]
    int jt = blockIdx.x, h = blockIdx.y, i = blockIdx.z;
    int tid = threadIdx.x, lane = tid & 31, w = tid >> 5;
    const float* base = qkv + (size_t)i * NSEQ * 384;

    for (int idx = tid; idx < 64 * 32; idx += 256) {
        int j = idx >> 5, d = idx & 31;
        Qs[d * 68 + j] = base[(size_t)(jt * 64 + j) * 384 + h * 32 + d];
    }
    for (int idx = tid; idx < 256 * 32; idx += 256) {
        int k = idx >> 5, d = idx & 31;
        Ks[d * 260 + k]  = base[(size_t)k * 384 + 128 + h * 32 + d];
        VsT[d * 264 + k] = base[(size_t)k * 384 + 256 + h * 32 + d];
    }
    __syncthreads();

    const float scale = 0.17677669529663687f;  // 1/sqrt(32)

    // ---- QK^T: warp w owns rows w*8..+7; thread owns cols lane*8..+7 ----
    float acc[8][8];
#pragma unroll
    for (int r = 0; r < 8; r++)
#pragma unroll
        for (int c = 0; c < 8; c++) acc[r][c] = 0.f;

#pragma unroll 4
    for (int d = 0; d < 32; d++) {
        float qr[8], kr[8];
        *(float4*)(qr)     = *(const float4*)&Qs[d * 68 + w * 8];
        *(float4*)(qr + 4) = *(const float4*)&Qs[d * 68 + w * 8 + 4];
        *(float4*)(kr)     = *(const float4*)&Ks[d * 260 + lane * 8];
        *(float4*)(kr + 4) = *(const float4*)&Ks[d * 260 + lane * 8 + 4];
#pragma unroll
        for (int r = 0; r < 8; r++)
#pragma unroll
            for (int c = 0; c < 8; c++)
                acc[r][c] += qr[r] * kr[c];
    }

    // ---- fused bias + softmax in registers, single S write ----
    int jrow0 = jt * 64 + w * 8;
#pragma unroll
    for (int r = 0; r < 8; r++) {
        const float* bm = biasmat + (size_t)(jrow0 + r) * 256 + lane * 8;
        float4 b0 = *(const float4*)bm;
        float4 b1 = *(const float4*)(bm + 4);
        float v[8];
        v[0] = fmaf(acc[r][0], scale, b0.x); v[1] = fmaf(acc[r][1], scale, b0.y);
        v[2] = fmaf(acc[r][2], scale, b0.z); v[3] = fmaf(acc[r][3], scale, b0.w);
        v[4] = fmaf(acc[r][4], scale, b1.x); v[5] = fmaf(acc[r][5], scale, b1.y);
        v[6] = fmaf(acc[r][6], scale, b1.z); v[7] = fmaf(acc[r][7], scale, b1.w);
        float mx = v[0];
#pragma unroll
        for (int q = 1; q < 8; q++) mx = fmaxf(mx, v[q]);
        mx = warp_max(mx);
        float sum = 0.f;
#pragma unroll
        for (int q = 0; q < 8; q++) { v[q] = __expf(v[q] - mx); sum += v[q]; }
        sum = warp_sum(sum);
        float inv = 1.0f / sum;
#pragma unroll
        for (int q = 0; q < 8; q++) v[q] *= inv;
        *(float4*)&S[(w * 8 + r) * 256 + lane * 8]     = *(float4*)(v);
        *(float4*)&S[(w * 8 + r) * 256 + lane * 8 + 4] = *(float4*)(v + 4);
    }
    __syncwarp();

    // ---- AV: V^T rows (d=lane), vectorized over k ----
    float o[8] = {};
    for (int k0 = 0; k0 < 256; k0 += 4) {
        float4 vv = *(const float4*)&VsT[lane * 264 + k0];
#pragma unroll
        for (int r = 0; r < 8; r++) {
            float4 wv = *(const float4*)&S[(w * 8 + r) * 256 + k0];
            o[r] += wv.x * vv.x + wv.y * vv.y + wv.z * vv.z + wv.w * vv.w;
        }
    }
#pragma unroll
    for (int r = 0; r < 8; r++)
        out[((size_t)i * NSEQ + jrow0 + r) * CDIM + h * 32 + lane] = o[r];
}

// ---------------- launch ----------------
extern "C" void kernel_launch(void* const* d_in, const int* in_sizes, int n_in,
                              void* d_out, int out_size) {
    const float* pair      = (const float*)d_in[0];
    const float* single    = (const float*)d_in[1];
    const unsigned char* mask = (const unsigned char*)d_in[2];
    const float* dist      = (const float*)d_in[3];
    const float* row_Wqkv  = (const float*)d_in[4];
    const float* row_bqkv  = (const float*)d_in[5];
    const float* row_Wo    = (const float*)d_in[6];
    const float* row_bo    = (const float*)d_in[7];
    const float* row_dsc   = (const float*)d_in[8];
    const float* col_Wqkv  = (const float*)d_in[9];
    const float* col_bqkv  = (const float*)d_in[10];
    const float* col_Wo    = (const float*)d_in[11];
    const float* col_bo    = (const float*)d_in[12];
    const float* col_dsc   = (const float*)d_in[13];
    const float* pnr_g     = (const float*)d_in[14];
    const float* pnr_b     = (const float*)d_in[15];
    const float* pnc_g     = (const float*)d_in[16];
    const float* pnc_b     = (const float*)d_in[17];
    const float* sn_g      = (const float*)d_in[18];
    const float* sn_b      = (const float*)d_in[19];
    const float* W1        = (const float*)d_in[20];
    const float* b1        = (const float*)d_in[21];
    const float* W2        = (const float*)d_in[22];
    const float* b2        = (const float*)d_in[23];

    float* pr = (float*)d_out;                               // [256,256,128]
    float* sr = pr + (size_t)NROWS * CDIM;                   // [256,128]

    float *qkv_p, *attn_p, *h1_p, *h2_p, *brow_p, *bcol_p;
    cudaGetSymbolAddress((void**)&qkv_p, g_qkv);
    cudaGetSymbolAddress((void**)&attn_p, g_attn);
    cudaGetSymbolAddress((void**)&h1_p, g_h1);
    cudaGetSymbolAddress((void**)&h2_p, g_h2);
    cudaGetSymbolAddress((void**)&brow_p, g_bias_row);
    cudaGetSymbolAddress((void**)&bcol_p, g_bias_col);

    cudaFuncSetAttribute(attn_tile_kernel, cudaFuncAttributeMaxDynamicSharedMemorySize,
                         ATT_SMEM_BYTES);

    // mask detection + fused bias tables
    maskbias_kernel<<<1, 1024>>>(mask, dist, row_dsc, col_dsc);

    // ---- stage 1: pr = LN(pair + tri_update_out(pair, single)) ----
    rowsum_kernel<<<NSEQ, CDIM>>>(pair);
    trimix_ln_kernel<<<NROWS / 8, 256>>>(pr, pair, single, pnr_g, pnr_b, 0);

    // ---- stage 2: pr = LN(pr + row_attn(pr)) ----
    gemm128_kernel<<<dim3(3, 512), 256>>>(pr, row_Wqkv, row_bqkv, qkv_p, NROWS, 384, 128, 0);
    attn_tile_kernel<<<dim3(4, NHEAD, NSEQ), 256, ATT_SMEM_BYTES>>>(qkv_p, brow_p, attn_p);
    gemm_wo_ln_kernel<<<512, 256>>>(attn_p, row_Wo, row_bo, pr, pnr_g, pnr_b, pr);

    // ---- stage 3: pr = LN(pr + tri_update_in(pr, single)) ----
    colsum_kernel<<<NSEQ, CDIM>>>(pr);
    trimix_ln_kernel<<<NROWS / 8, 256>>>(pr, pr, single, pnc_g, pnc_b, 1);

    // ---- stage 4: pr = LN(pr + col_attn(pr)) ----
    gemm128_kernel<<<dim3(3, 512), 256>>>(pr, col_Wqkv, col_bqkv, qkv_p, NROWS, 384, 128, 0);
    attn_tile_kernel<<<dim3(4, NHEAD, NSEQ), 256, ATT_SMEM_BYTES>>>(qkv_p, bcol_p, attn_p);
    gemm_wo_ln_kernel<<<512, 256>>>(attn_p, col_Wo, col_bo, pr, pnc_g, pnc_b, pr);

    // ---- single-rep MLP + LN ----
    gemm128_kernel<<<dim3(2, 2), 256>>>(single, W1, b1, h1_p, NSEQ, 256, 128, 1);
    gemm128_kernel<<<dim3(1, 2), 256>>>(h1_p, W2, b2, h2_p, NSEQ, 128, 256, 1);
    residual_ln_kernel<<<NSEQ / 8, 256>>>(sr, single, h2_p, sn_g, sn_b, NSEQ);
}

// round 9
// speedup vs baseline: 1.4757x; 1.0723x over previous
#include <cuda_runtime.h>
#include <math.h>

#define NSEQ 256
#define CDIM 128
#define NHEAD 4
#define DHEAD 32
#define NROWS (NSEQ * NSEQ)

// ---------------- scratch (device globals; no allocation allowed) ----------------
__device__ float g_qkv[(size_t)NROWS * 3 * CDIM];   // 96 MB
__device__ float g_attn[(size_t)NROWS * CDIM];      // 32 MB
__device__ float g_sums[NSEQ * CDIM];               // row/col prefix sums
__device__ float g_h1[NSEQ * 2 * CDIM];
__device__ float g_h2[NSEQ * CDIM];
__device__ float g_bias_row[NSEQ * NSEQ];           // dscale*dist with mask folded
__device__ float g_bias_col[NSEQ * NSEQ];

// ---------------- helpers ----------------
__device__ __forceinline__ float warp_sum(float v) {
#pragma unroll
    for (int o = 16; o; o >>= 1) v += __shfl_xor_sync(0xffffffffu, v, o);
    return v;
}
__device__ __forceinline__ float warp_max(float v) {
#pragma unroll
    for (int o = 16; o; o >>= 1) v = fmaxf(v, __shfl_xor_sync(0xffffffffu, v, o));
    return v;
}
__device__ __forceinline__ float half16_sum(float v) {
#pragma unroll
    for (int o = 8; o; o >>= 1) v += __shfl_xor_sync(0xffffffffu, v, o);
    return v;
}

// ---------------- mask detect + fused bias tables ----------------
__global__ void maskbias_kernel(const unsigned char* __restrict__ m,
                                const float* __restrict__ dist,
                                const float* __restrict__ rdsc,
                                const float* __restrict__ cdsc) {
    __shared__ int flag;
    int tid = threadIdx.x;
    if (tid == 0) flag = 0;
    __syncthreads();
    int local = 0;
    for (int idx = tid; idx < NSEQ * NSEQ; idx += blockDim.x)
        if ((idx & 3) && m[idx]) local = 1;
    if (local) atomicOr(&flag, 1);
    __syncthreads();
    int isBytes = flag;
    float rs = rdsc[0], cs = cdsc[0];
    for (int idx = tid; idx < NSEQ * NSEQ; idx += blockDim.x) {
        int t = (idx & 255) * 256 + (idx >> 8);
        unsigned char mb = isBytes ? m[idx] : m[4 * (size_t)idx];
        unsigned char mt = isBytes ? m[t] : m[4 * (size_t)t];
        float dv = dist[idx];
        g_bias_row[idx] = mb ? -1e30f : rs * dv;
        g_bias_col[idx] = mt ? -1e30f : cs * dv;
    }
}

// ---------------- prefix sums ----------------
__global__ void rowsum_kernel(const float* __restrict__ pair) {
    int i = blockIdx.x, c = threadIdx.x;
    const float* p = pair + (size_t)i * NSEQ * CDIM + c;
    float s = 0.f;
#pragma unroll 4
    for (int k = 0; k < i; k++) s += __ldg(&p[(size_t)k * CDIM]);
    g_sums[i * CDIM + c] = s;
}

__global__ void colsum_kernel(const float* __restrict__ pr) {
    int j = blockIdx.x, c = threadIdx.x;
    const float* p = pr + (size_t)j * CDIM + c;
    float s = 0.f;
#pragma unroll 4
    for (int k = 0; k < j; k++) s += __ldg(&p[(size_t)k * NSEQ * CDIM]);
    g_sums[j * CDIM + c] = s;
}

// ---------------- fused tri-update + LayerNorm (warp per (i,j) row) ----------------
__global__ __launch_bounds__(256)
void trimix_ln_kernel(float* __restrict__ out, const float* __restrict__ src,
                      const float* __restrict__ single,
                      const float* __restrict__ g, const float* __restrict__ b,
                      int mode) {
    int lane = threadIdx.x & 31, warp = threadIdx.x >> 5;
    int row = blockIdx.x * 8 + warp;
    int i = row >> 8, j = row & 255;
    const float* sA = single + (size_t)(mode == 0 ? j : i) * CDIM;
    const float* sB = g_sums + (size_t)(mode == 0 ? i : j) * CDIM;
    const float* xr = src + (size_t)row * CDIM;

    float v[4];
    float mean = 0.f;
#pragma unroll
    for (int q = 0; q < 4; q++) {
        int c = q * 32 + lane;
        v[q] = xr[c] + sA[c] + sB[c];
        mean += v[q];
    }
    mean = warp_sum(mean) * (1.0f / CDIM);
    float var = 0.f;
#pragma unroll
    for (int q = 0; q < 4; q++) { float d = v[q] - mean; var += d * d; }
    var = warp_sum(var) * (1.0f / CDIM);
    float inv = rsqrtf(var + 1e-5f);
    float* orow = out + (size_t)row * CDIM;
#pragma unroll
    for (int q = 0; q < 4; q++) {
        int c = q * 32 + lane;
        orow[c] = (v[q] - mean) * inv * g[c] + b[c];
    }
}

__global__ __launch_bounds__(256)
void residual_ln_kernel(float* __restrict__ out, const float* __restrict__ x,
                        const float* __restrict__ y,
                        const float* __restrict__ g, const float* __restrict__ b,
                        int nrows) {
    int lane = threadIdx.x & 31, warp = threadIdx.x >> 5;
    int row = blockIdx.x * 8 + warp;
    if (row >= nrows) return;
    const float* xr = x + (size_t)row * CDIM;
    const float* yr = y + (size_t)row * CDIM;
    float v[4];
    float mean = 0.f;
#pragma unroll
    for (int q = 0; q < 4; q++) {
        int c = q * 32 + lane;
        v[q] = xr[c] + yr[c];
        mean += v[q];
    }
    mean = warp_sum(mean) * (1.0f / CDIM);
    float var = 0.f;
#pragma unroll
    for (int q = 0; q < 4; q++) { float d = v[q] - mean; var += d * d; }
    var = warp_sum(var) * (1.0f / CDIM);
    float inv = rsqrtf(var + 1e-5f);
    float* orow = out + (size_t)row * CDIM;
#pragma unroll
    for (int q = 0; q < 4; q++) {
        int c = q * 32 + lane;
        orow[c] = (v[q] - mean) * inv * g[c] + b[c];
    }
}

// ---------------- double-buffered SGEMM 128x128x16, 8x8 per thread ----------------
__global__ __launch_bounds__(256)
void gemm128_kernel(const float* __restrict__ A, const float* __restrict__ B,
                    const float* __restrict__ bias, float* __restrict__ C,
                    int M, int N, int K, int relu) {
    __shared__ float As[2][16][128];
    __shared__ float Bs[2][16][132];
    int tid = threadIdx.x;
    int m0 = blockIdx.y * 128, n0 = blockIdx.x * 128;
    int tx = tid & 15, ty = tid >> 4;
    int arow = tid >> 1, acolg = (tid & 1) << 3;
    int brow = tid >> 5, bcol = (tid & 31) << 2;
    const float* Aptr = A + (size_t)(m0 + arow) * K;

    {
        float4 a0 = *(const float4*)&Aptr[acolg];
        float4 a1 = *(const float4*)&Aptr[acolg + 4];
        As[0][acolg + 0][arow] = a0.x; As[0][acolg + 1][arow] = a0.y;
        As[0][acolg + 2][arow] = a0.z; As[0][acolg + 3][arow] = a0.w;
        As[0][acolg + 4][arow] = a1.x; As[0][acolg + 5][arow] = a1.y;
        As[0][acolg + 6][arow] = a1.z; As[0][acolg + 7][arow] = a1.w;
        *(float4*)&Bs[0][brow][bcol]     = *(const float4*)&B[(size_t)brow * N + n0 + bcol];
        *(float4*)&Bs[0][brow + 8][bcol] = *(const float4*)&B[(size_t)(brow + 8) * N + n0 + bcol];
    }
    __syncthreads();

    float acc[8][8] = {};
    int buf = 0;
    for (int k0 = 16; k0 < K; k0 += 16) {
        float4 na0 = *(const float4*)&Aptr[k0 + acolg];
        float4 na1 = *(const float4*)&Aptr[k0 + acolg + 4];
        float4 nb0 = *(const float4*)&B[(size_t)(k0 + brow) * N + n0 + bcol];
        float4 nb1 = *(const float4*)&B[(size_t)(k0 + brow + 8) * N + n0 + bcol];
#pragma unroll
        for (int kk = 0; kk < 16; kk++) {
            float a[8], b[8];
            *(float4*)(a)     = *(const float4*)&As[buf][kk][ty * 8];
            *(float4*)(a + 4) = *(const float4*)&As[buf][kk][ty * 8 + 4];
            *(float4*)(b)     = *(const float4*)&Bs[buf][kk][tx * 8];
            *(float4*)(b + 4) = *(const float4*)&Bs[buf][kk][tx * 8 + 4];
#pragma unroll
            for (int i2 = 0; i2 < 8; i2++)
#pragma unroll
                for (int j2 = 0; j2 < 8; j2++)
                    acc[i2][j2] += a[i2] * b[j2];
        }
        int nb = buf ^ 1;
        As[nb][acolg + 0][arow] = na0.x; As[nb][acolg + 1][arow] = na0.y;
        As[nb][acolg + 2][arow] = na0.z; As[nb][acolg + 3][arow] = na0.w;
        As[nb][acolg + 4][arow] = na1.x; As[nb][acolg + 5][arow] = na1.y;
        As[nb][acolg + 6][arow] = na1.z; As[nb][acolg + 7][arow] = na1.w;
        *(float4*)&Bs[nb][brow][bcol]     = nb0;
        *(float4*)&Bs[nb][brow + 8][bcol] = nb1;
        __syncthreads();
        buf = nb;
    }
#pragma unroll
    for (int kk = 0; kk < 16; kk++) {
        float a[8], b[8];
        *(float4*)(a)     = *(const float4*)&As[buf][kk][ty * 8];
        *(float4*)(a + 4) = *(const float4*)&As[buf][kk][ty * 8 + 4];
        *(float4*)(b)     = *(const float4*)&Bs[buf][kk][tx * 8];
        *(float4*)(b + 4) = *(const float4*)&Bs[buf][kk][tx * 8 + 4];
#pragma unroll
        for (int i2 = 0; i2 < 8; i2++)
#pragma unroll
            for (int j2 = 0; j2 < 8; j2++)
                acc[i2][j2] += a[i2] * b[j2];
    }

    float4 bi0 = *(const float4*)&bias[n0 + tx * 8];
    float4 bi1 = *(const float4*)&bias[n0 + tx * 8 + 4];
#pragma unroll
    for (int r = 0; r < 8; r++) {
        float* crow = C + (size_t)(m0 + ty * 8 + r) * N + n0 + tx * 8;
        float4 o0 = make_float4(acc[r][0] + bi0.x, acc[r][1] + bi0.y,
                                acc[r][2] + bi0.z, acc[r][3] + bi0.w);
        float4 o1 = make_float4(acc[r][4] + bi1.x, acc[r][5] + bi1.y,
                                acc[r][6] + bi1.z, acc[r][7] + bi1.w);
        if (relu) {
            o0.x = fmaxf(o0.x, 0.f); o0.y = fmaxf(o0.y, 0.f);
            o0.z = fmaxf(o0.z, 0.f); o0.w = fmaxf(o0.w, 0.f);
            o1.x = fmaxf(o1.x, 0.f); o1.y = fmaxf(o1.y, 0.f);
            o1.z = fmaxf(o1.z, 0.f); o1.w = fmaxf(o1.w, 0.f);
        }
        *(float4*)crow = o0;
        *(float4*)(crow + 4) = o1;
    }
}

// ---------------- fused out-proj + residual + LayerNorm (N=K=128) ----------------
__global__ __launch_bounds__(256)
void gemm_wo_ln_kernel(const float* __restrict__ A, const float* __restrict__ B,
                       const float* __restrict__ bias, const float* __restrict__ xres,
                       const float* __restrict__ g, const float* __restrict__ bb,
                       float* __restrict__ out) {
    __shared__ float As[2][16][128];
    __shared__ float Bs[2][16][132];
    int tid = threadIdx.x;
    int m0 = blockIdx.x * 128;
    int tx = tid & 15, ty = tid >> 4;
    int arow = tid >> 1, acolg = (tid & 1) << 3;
    int brow = tid >> 5, bcol = (tid & 31) << 2;
    const float* Aptr = A + (size_t)(m0 + arow) * 128;

    {
        float4 a0 = *(const float4*)&Aptr[acolg];
        float4 a1 = *(const float4*)&Aptr[acolg + 4];
        As[0][acolg + 0][arow] = a0.x; As[0][acolg + 1][arow] = a0.y;
        As[0][acolg + 2][arow] = a0.z; As[0][acolg + 3][arow] = a0.w;
        As[0][acolg + 4][arow] = a1.x; As[0][acolg + 5][arow] = a1.y;
        As[0][acolg + 6][arow] = a1.z; As[0][acolg + 7][arow] = a1.w;
        *(float4*)&Bs[0][brow][bcol]     = *(const float4*)&B[(size_t)brow * 128 + bcol];
        *(float4*)&Bs[0][brow + 8][bcol] = *(const float4*)&B[(size_t)(brow + 8) * 128 + bcol];
    }
    __syncthreads();

    float acc[8][8] = {};
    int buf = 0;
    for (int k0 = 16; k0 < 128; k0 += 16) {
        float4 na0 = *(const float4*)&Aptr[k0 + acolg];
        float4 na1 = *(const float4*)&Aptr[k0 + acolg + 4];
        float4 nb0 = *(const float4*)&B[(size_t)(k0 + brow) * 128 + bcol];
        float4 nb1 = *(const float4*)&B[(size_t)(k0 + brow + 8) * 128 + bcol];
#pragma unroll
        for (int kk = 0; kk < 16; kk++) {
            float a[8], b[8];
            *(float4*)(a)     = *(const float4*)&As[buf][kk][ty * 8];
            *(float4*)(a + 4) = *(const float4*)&As[buf][kk][ty * 8 + 4];
            *(float4*)(b)     = *(const float4*)&Bs[buf][kk][tx * 8];
            *(float4*)(b + 4) = *(const float4*)&Bs[buf][kk][tx * 8 + 4];
#pragma unroll
            for (int i2 = 0; i2 < 8; i2++)
#pragma unroll
                for (int j2 = 0; j2 < 8; j2++)
                    acc[i2][j2] += a[i2] * b[j2];
        }
        int nb = buf ^ 1;
        As[nb][acolg + 0][arow] = na0.x; As[nb][acolg + 1][arow] = na0.y;
        As[nb][acolg + 2][arow] = na0.z; As[nb][acolg + 3][arow] = na0.w;
        As[nb][acolg + 4][arow] = na1.x; As[nb][acolg + 5][arow] = na1.y;
        As[nb][acolg + 6][arow] = na1.z; As[nb][acolg + 7][arow] = na1.w;
        *(float4*)&Bs[nb][brow][bcol]     = nb0;
        *(float4*)&Bs[nb][brow + 8][bcol] = nb1;
        __syncthreads();
        buf = nb;
    }
#pragma unroll
    for (int kk = 0; kk < 16; kk++) {
        float a[8], b[8];
        *(float4*)(a)     = *(const float4*)&As[buf][kk][ty * 8];
        *(float4*)(a + 4) = *(const float4*)&As[buf][kk][ty * 8 + 4];
        *(float4*)(b)     = *(const float4*)&Bs[buf][kk][tx * 8];
        *(float4*)(b + 4) = *(const float4*)&Bs[buf][kk][tx * 8 + 4];
#pragma unroll
        for (int i2 = 0; i2 < 8; i2++)
#pragma unroll
            for (int j2 = 0; j2 < 8; j2++)
                acc[i2][j2] += a[i2] * b[j2];
    }

    float4 bi0 = *(const float4*)&bias[tx * 8];
    float4 bi1 = *(const float4*)&bias[tx * 8 + 4];
    float4 g0  = *(const float4*)&g[tx * 8];
    float4 g1  = *(const float4*)&g[tx * 8 + 4];
    float4 be0 = *(const float4*)&bb[tx * 8];
    float4 be1 = *(const float4*)&bb[tx * 8 + 4];
#pragma unroll
    for (int r = 0; r < 8; r++) {
        int row = m0 + ty * 8 + r;
        const float* xr = xres + (size_t)row * 128 + tx * 8;
        float4 x0 = *(const float4*)xr;
        float4 x1 = *(const float4*)(xr + 4);
        float v[8];
        v[0] = acc[r][0] + bi0.x + x0.x; v[1] = acc[r][1] + bi0.y + x0.y;
        v[2] = acc[r][2] + bi0.z + x0.z; v[3] = acc[r][3] + bi0.w + x0.w;
        v[4] = acc[r][4] + bi1.x + x1.x; v[5] = acc[r][5] + bi1.y + x1.y;
        v[6] = acc[r][6] + bi1.z + x1.z; v[7] = acc[r][7] + bi1.w + x1.w;
        float s = 0.f;
#pragma unroll
        for (int q = 0; q < 8; q++) s += v[q];
        s = half16_sum(s);
        float mean = s * (1.0f / 128.0f);
        float d2 = 0.f;
#pragma unroll
        for (int q = 0; q < 8; q++) { float d = v[q] - mean; d2 += d * d; }
        d2 = half16_sum(d2);
        float inv = rsqrtf(d2 * (1.0f / 128.0f) + 1e-5f);
        float* orow = out + (size_t)row * 128 + tx * 8;
        float4 o0, o1;
        o0.x = (v[0] - mean) * inv * g0.x + be0.x;
        o0.y = (v[1] - mean) * inv * g0.y + be0.y;
        o0.z = (v[2] - mean) * inv * g0.z + be0.z;
        o0.w = (v[3] - mean) * inv * g0.w + be0.w;
        o1.x = (v[4] - mean) * inv * g1.x + be1.x;
        o1.y = (v[5] - mean) * inv * g1.y + be1.y;
        o1.z = (v[6] - mean) * inv * g1.z + be1.z;
        o1.w = (v[7] - mean) * inv * g1.w + be1.w;
        *(float4*)orow = o0;
        *(float4*)(orow + 4) = o1;
    }
}

// ---------------- tiled attention: block per (jt, h, i), 64 j-rows per block ----------------
// smem floats: Qs[32][68] | Ks[32][260] | Vs[256][33] | S[64][256]
// Thread (w,lane): rows w*8..+7, cols {lane*4..+3} U {128+lane*4..+3} (conflict-free phases)
#define ATT_QS 0
#define ATT_KS 2176
#define ATT_VS (ATT_KS + 32 * 260)
#define ATT_S  (ATT_VS + 256 * 33)
#define ATT_FLOATS (ATT_S + 64 * 256)
#define ATT_SMEM_BYTES (ATT_FLOATS * 4)

__global__ __launch_bounds__(256)
void attn_tile_kernel(const float* __restrict__ qkv, const float* __restrict__ biasmat,
                      float* __restrict__ out) {
    extern __shared__ float sh[];
    float* Qs = sh + ATT_QS;   // Q^T [d][j]
    float* Ks = sh + ATT_KS;   // K^T [d][k] stride 260
    float* Vs = sh + ATT_VS;   // V  [k][d] stride 33
    float* S  = sh + ATT_S;    // exp-weights [j][k]
    int jt = blockIdx.x, h = blockIdx.y, i = blockIdx.z;
    int tid = threadIdx.x, lane = tid & 31, w = tid >> 5;
    const float* base = qkv + (size_t)i * NSEQ * 384;

    for (int idx = tid; idx < 64 * 32; idx += 256) {
        int j = idx >> 5, d = idx & 31;
        Qs[d * 68 + j] = base[(size_t)(jt * 64 + j) * 384 + h * 32 + d];
    }
    for (int idx = tid; idx < 256 * 32; idx += 256) {
        int k = idx >> 5, d = idx & 31;
        Ks[d * 260 + k] = base[(size_t)k * 384 + 128 + h * 32 + d];
        Vs[k * 33 + d]  = base[(size_t)k * 384 + 256 + h * 32 + d];
    }
    __syncthreads();

    const float scale = 0.17677669529663687f;  // 1/sqrt(32)

    // ---- QK^T ----
    float acc[8][8];
#pragma unroll
    for (int r = 0; r < 8; r++)
#pragma unroll
        for (int c = 0; c < 8; c++) acc[r][c] = 0.f;

#pragma unroll 4
    for (int d = 0; d < 32; d++) {
        float qr[8], kr[8];
        *(float4*)(qr)     = *(const float4*)&Qs[d * 68 + w * 8];       // broadcast
        *(float4*)(qr + 4) = *(const float4*)&Qs[d * 68 + w * 8 + 4];   // broadcast
        *(float4*)(kr)     = *(const float4*)&Ks[d * 260 + lane * 4];        // conflict-free
        *(float4*)(kr + 4) = *(const float4*)&Ks[d * 260 + 128 + lane * 4];  // conflict-free
#pragma unroll
        for (int r = 0; r < 8; r++)
#pragma unroll
            for (int c = 0; c < 8; c++)
                acc[r][c] += qr[r] * kr[c];
    }

    // ---- fused bias + softmax in registers; store unnormalized exp, keep 1/sum ----
    int jrow0 = jt * 64 + w * 8;
    float invs[8];
#pragma unroll
    for (int r = 0; r < 8; r++) {
        const float* bm = biasmat + (size_t)(jrow0 + r) * 256;
        float4 b0 = __ldg((const float4*)(bm + lane * 4));
        float4 b1 = __ldg((const float4*)(bm + 128 + lane * 4));
        float v[8];
        v[0] = fmaf(acc[r][0], scale, b0.x); v[1] = fmaf(acc[r][1], scale, b0.y);
        v[2] = fmaf(acc[r][2], scale, b0.z); v[3] = fmaf(acc[r][3], scale, b0.w);
        v[4] = fmaf(acc[r][4], scale, b1.x); v[5] = fmaf(acc[r][5], scale, b1.y);
        v[6] = fmaf(acc[r][6], scale, b1.z); v[7] = fmaf(acc[r][7], scale, b1.w);
        float mx = v[0];
#pragma unroll
        for (int q = 1; q < 8; q++) mx = fmaxf(mx, v[q]);
        mx = warp_max(mx);
        float sum = 0.f;
#pragma unroll
        for (int q = 0; q < 8; q++) { v[q] = __expf(v[q] - mx); sum += v[q]; }
        sum = warp_sum(sum);
        invs[r] = 1.0f / sum;
        *(float4*)&S[(w * 8 + r) * 256 + lane * 4]       = *(float4*)(v);
        *(float4*)&S[(w * 8 + r) * 256 + 128 + lane * 4] = *(float4*)(v + 4);
    }
    __syncwarp();

    // ---- AV: scalar V loads (conflict-free), broadcast S rows ----
    float o[8] = {};
    for (int k0 = 0; k0 < 256; k0 += 4) {
        float v0 = Vs[(k0 + 0) * 33 + lane];
        float v1 = Vs[(k0 + 1) * 33 + lane];
        float v2 = Vs[(k0 + 2) * 33 + lane];
        float v3 = Vs[(k0 + 3) * 33 + lane];
#pragma unroll
        for (int r = 0; r < 8; r++) {
            float4 wv = *(const float4*)&S[(w * 8 + r) * 256 + k0];  // broadcast
            o[r] += wv.x * v0 + wv.y * v1 + wv.z * v2 + wv.w * v3;
        }
    }
#pragma unroll
    for (int r = 0; r < 8; r++)
        out[((size_t)i * NSEQ + jrow0 + r) * CDIM + h * 32 + lane] = o[r] * invs[r];
}

// ---------------- launch ----------------
extern "C" void kernel_launch(void* const* d_in, const int* in_sizes, int n_in,
                              void* d_out, int out_size) {
    const float* pair      = (const float*)d_in[0];
    const float* single    = (const float*)d_in[1];
    const unsigned char* mask = (const unsigned char*)d_in[2];
    const float* dist      = (const float*)d_in[3];
    const float* row_Wqkv  = (const float*)d_in[4];
    const float* row_bqkv  = (const float*)d_in[5];
    const float* row_Wo    = (const float*)d_in[6];
    const float* row_bo    = (const float*)d_in[7];
    const float* row_dsc   = (const float*)d_in[8];
    const float* col_Wqkv  = (const float*)d_in[9];
    const float* col_bqkv  = (const float*)d_in[10];
    const float* col_Wo    = (const float*)d_in[11];
    const float* col_bo    = (const float*)d_in[12];
    const float* col_dsc   = (const float*)d_in[13];
    const float* pnr_g     = (const float*)d_in[14];
    const float* pnr_b     = (const float*)d_in[15];
    const float* pnc_g     = (const float*)d_in[16];
    const float* pnc_b     = (const float*)d_in[17];
    const float* sn_g      = (const float*)d_in[18];
    const float* sn_b      = (const float*)d_in[19];
    const float* W1        = (const float*)d_in[20];
    const float* b1        = (const float*)d_in[21];
    const float* W2        = (const float*)d_in[22];
    const float* b2        = (const float*)d_in[23];

    float* pr = (float*)d_out;                               // [256,256,128]
    float* sr = pr + (size_t)NROWS * CDIM;                   // [256,128]

    float *qkv_p, *attn_p, *h1_p, *h2_p, *brow_p, *bcol_p;
    cudaGetSymbolAddress((void**)&qkv_p, g_qkv);
    cudaGetSymbolAddress((void**)&attn_p, g_attn);
    cudaGetSymbolAddress((void**)&h1_p, g_h1);
    cudaGetSymbolAddress((void**)&h2_p, g_h2);
    cudaGetSymbolAddress((void**)&brow_p, g_bias_row);
    cudaGetSymbolAddress((void**)&bcol_p, g_bias_col);

    cudaFuncSetAttribute(attn_tile_kernel, cudaFuncAttributeMaxDynamicSharedMemorySize,
                         ATT_SMEM_BYTES);

    // mask detection + fused bias tables
    maskbias_kernel<<<1, 1024>>>(mask, dist, row_dsc, col_dsc);

    // ---- stage 1: pr = LN(pair + tri_update_out(pair, single)) ----
    rowsum_kernel<<<NSEQ, CDIM>>>(pair);
    trimix_ln_kernel<<<NROWS / 8, 256>>>(pr, pair, single, pnr_g, pnr_b, 0);

    // ---- stage 2: pr = LN(pr + row_attn(pr)) ----
    gemm128_kernel<<<dim3(3, 512), 256>>>(pr, row_Wqkv, row_bqkv, qkv_p, NROWS, 384, 128, 0);
    attn_tile_kernel<<<dim3(4, NHEAD, NSEQ), 256, ATT_SMEM_BYTES>>>(qkv_p, brow_p, attn_p);
    gemm_wo_ln_kernel<<<512, 256>>>(attn_p, row_Wo, row_bo, pr, pnr_g, pnr_b, pr);

    // ---- stage 3: pr = LN(pr + tri_update_in(pr, single)) ----
    colsum_kernel<<<NSEQ, CDIM>>>(pr);
    trimix_ln_kernel<<<NROWS / 8, 256>>>(pr, pr, single, pnc_g, pnc_b, 1);

    // ---- stage 4: pr = LN(pr + col_attn(pr)) ----
    gemm128_kernel<<<dim3(3, 512), 256>>>(pr, col_Wqkv, col_bqkv, qkv_p, NROWS, 384, 128, 0);
    attn_tile_kernel<<<dim3(4, NHEAD, NSEQ), 256, ATT_SMEM_BYTES>>>(qkv_p, bcol_p, attn_p);
    gemm_wo_ln_kernel<<<512, 256>>>(attn_p, col_Wo, col_bo, pr, pnc_g, pnc_b, pr);

    // ---- single-rep MLP + LN ----
    gemm128_kernel<<<dim3(2, 2), 256>>>(single, W1, b1, h1_p, NSEQ, 256, 128, 1);
    gemm128_kernel<<<dim3(1, 2), 256>>>(h1_p, W2, b2, h2_p, NSEQ, 128, 256, 1);
    residual_ln_kernel<<<NSEQ / 8, 256>>>(sr, single, h2_p, sn_g, sn_b, NSEQ);
}